// round 9
// baseline (speedup 1.0000x reference)
#include <cuda_runtime.h>
#include <cuda_bf16.h>
#include <cstdint>

static constexpr int M_TOTAL = 16384;
static constexpr int K = 512;
static constexpr int N = 512;
static constexpr int G = 8;

#define BM 128
#define BN 128
#define KC 64               // K chunk: 64 bf16 = 128 bytes/row (SW128 atom)
#define NTHREADS 512

// ---- pre-split scratch ----
__device__ __nv_bfloat16 g_Ath[(size_t)M_TOTAL * K];
__device__ __nv_bfloat16 g_Atl[(size_t)M_TOTAL * K];
__device__ __nv_bfloat16 g_Bth[(size_t)G * N * K];
__device__ __nv_bfloat16 g_Btl[(size_t)G * N * K];

// ============================ helpers ============================

__device__ __forceinline__ uint32_t smem_u32(const void* p) {
    uint32_t a;
    asm("{ .reg .u64 t; cvta.to.shared.u64 t, %1; cvt.u32.u64 %0, t; }"
        : "=r"(a) : "l"(p));
    return a;
}

__device__ __forceinline__ void ldsm_x4(uint32_t* r, uint32_t addr) {
    asm volatile("ldmatrix.sync.aligned.m8n8.x4.shared.b16 {%0,%1,%2,%3}, [%4];"
                 : "=r"(r[0]), "=r"(r[1]), "=r"(r[2]), "=r"(r[3]) : "r"(addr));
}

__device__ __forceinline__ void mma16816(float* d, const uint32_t* a, const uint32_t* b) {
    asm volatile(
        "mma.sync.aligned.m16n8k16.row.col.f32.bf16.bf16.f32 "
        "{%0,%1,%2,%3}, {%4,%5,%6,%7}, {%8,%9}, {%0,%1,%2,%3};"
        : "+f"(d[0]), "+f"(d[1]), "+f"(d[2]), "+f"(d[3])
        : "r"(a[0]), "r"(a[1]), "r"(a[2]), "r"(a[3]), "r"(b[0]), "r"(b[1]));
}

__device__ __forceinline__ uint32_t swz128(uint32_t b) {
    return b ^ ((b >> 3) & 0x70);
}

__device__ __forceinline__ void cp16(uint32_t smem_dst, const void* gsrc, uint32_t srcbytes) {
    asm volatile("cp.async.cg.shared.global [%0], [%1], 16, %2;"
                 :: "r"(smem_dst), "l"(gsrc), "r"(srcbytes) : "memory");
}
__device__ __forceinline__ void cp16(uint32_t smem_dst, const void* gsrc) {
    asm volatile("cp.async.cg.shared.global [%0], [%1], 16;"
                 :: "r"(smem_dst), "l"(gsrc) : "memory");
}

// ============================ kernel 1a: A bf16 split ============================

__global__ __launch_bounds__(256)
void a_split(const float* __restrict__ A) {
    const size_t idx = (size_t)blockIdx.x * 256 + threadIdx.x;   // float4 index
    const float4 v = reinterpret_cast<const float4*>(A)[idx];
    __nv_bfloat16 hx = __float2bfloat16(v.x);
    __nv_bfloat16 hy = __float2bfloat16(v.y);
    __nv_bfloat16 hz = __float2bfloat16(v.z);
    __nv_bfloat16 hw = __float2bfloat16(v.w);
    __nv_bfloat16 lx = __float2bfloat16(v.x - __bfloat162float(hx));
    __nv_bfloat16 ly = __float2bfloat16(v.y - __bfloat162float(hy));
    __nv_bfloat16 lz = __float2bfloat16(v.z - __bfloat162float(hz));
    __nv_bfloat16 lw = __float2bfloat16(v.w - __bfloat162float(hw));
    uint32_t h01, h23, l01, l23;
    asm("mov.b32 %0, {%1, %2};" : "=r"(h01) : "h"(__nv_bfloat16_raw(hx).x), "h"(__nv_bfloat16_raw(hy).x));
    asm("mov.b32 %0, {%1, %2};" : "=r"(h23) : "h"(__nv_bfloat16_raw(hz).x), "h"(__nv_bfloat16_raw(hw).x));
    asm("mov.b32 %0, {%1, %2};" : "=r"(l01) : "h"(__nv_bfloat16_raw(lx).x), "h"(__nv_bfloat16_raw(ly).x));
    asm("mov.b32 %0, {%1, %2};" : "=r"(l23) : "h"(__nv_bfloat16_raw(lz).x), "h"(__nv_bfloat16_raw(lw).x));
    reinterpret_cast<uint2*>(g_Ath)[idx] = make_uint2(h01, h23);
    reinterpret_cast<uint2*>(g_Atl)[idx] = make_uint2(l01, l23);
}

// ============================ kernel 1b: B transpose + bf16 split ============================

__global__ __launch_bounds__(256)
void b_transpose_split(const float* __restrict__ B) {
    __shared__ float t[32][33];
    const int g  = blockIdx.z;
    const int k0 = blockIdx.y * 32;
    const int n0 = blockIdx.x * 32;
    const int x = threadIdx.x;
    const int y = threadIdx.y;
    const float* Bg = B + (size_t)g * K * N;
    #pragma unroll
    for (int i = 0; i < 4; i++)
        t[y + 8 * i][x] = Bg[(size_t)(k0 + y + 8 * i) * N + n0 + x];
    __syncthreads();
    #pragma unroll
    for (int i = 0; i < 4; i++) {
        const int n = n0 + y + 8 * i;
        const int k = k0 + x;
        float v = t[x][y + 8 * i];
        __nv_bfloat16 hi = __float2bfloat16(v);
        __nv_bfloat16 lo = __float2bfloat16(v - __bfloat162float(hi));
        const size_t o = ((size_t)g * N + n) * K + k;
        g_Bth[o] = hi;
        g_Btl[o] = lo;
    }
}

// ============================ kernel 2: 3-stage pipelined grouped GEMM ============================

static constexpr int OFF_AH = 0;
static constexpr int OFF_AL = 16384;
static constexpr int OFF_BH = 2 * 16384;
static constexpr int OFF_BL = 3 * 16384;
static constexpr int STAGE  = 4 * 16384;          // 64 KB per stage
static constexpr int NSTAGE = 3;
static constexpr int SMEM_BYTES = 1024 /*align slack*/ + NSTAGE * STAGE;

__global__ __launch_bounds__(NTHREADS, 1)
void grouped_gemm_mma_kernel(const int* __restrict__ glist,
                             float*     __restrict__ C) {
    extern __shared__ char dynsmem[];
    const uint32_t raw   = smem_u32(dynsmem);
    const uint32_t sbase = (raw + 1023u) & ~1023u;

    const int tid  = threadIdx.x;
    const int wid  = tid >> 5;
    const int lane = tid & 31;
    const int warp_m = wid & 3;              // 0..3 -> 32-row slab
    const int warp_n = wid >> 2;             // 0..3 -> 32-col slab
    const int row0 = blockIdx.y * BM;
    const int col0 = blockIdx.x * BN;

    int gl[G];
    #pragma unroll
    for (int g = 0; g < G; g++) gl[g] = glist[g];
    auto gid_of = [&](int row) {
        int g = 0;
        #pragma unroll
        for (int i = 0; i < G; i++) if (row >= gl[i]) g = i + 1;
        return g;
    };
    const int g0 = gid_of(row0);
    const int g1 = gid_of(row0 + BM - 1);
    const int nchunks = (g1 - g0 + 1) * (K / KC);

    auto issue_chunk = [&](int c, int s) {
        const int g  = g0 + (c >> 3);             // K/KC == 8
        const int kt = (c & 7) * KC;
        const int glo = (g == 0) ? 0 : gl[g - 1];
        const int ghi = gl[g];
        const __nv_bfloat16* __restrict__ Ah = g_Ath + kt;
        const __nv_bfloat16* __restrict__ Al = g_Atl + kt;
        const __nv_bfloat16* __restrict__ Bh = g_Bth + ((size_t)g * N + col0) * K + kt;
        const __nv_bfloat16* __restrict__ Bl = g_Btl + ((size_t)g * N + col0) * K + kt;
        const uint32_t stb = sbase + (uint32_t)(s * STAGE);
        #pragma unroll
        for (int i = 0; i < 2; i++) {
            const int idx = tid + i * NTHREADS;   // 0..1023
            const int r = idx >> 3;               // row 0..127
            const int q = idx & 7;                // 16B chunk 0..7
            const uint32_t dsw = swz128((uint32_t)(r * 128 + q * 16));
            const int grow = row0 + r;
            const uint32_t asz = (grow >= glo && grow < ghi) ? 16u : 0u;
            cp16(stb + OFF_AH + dsw, Ah + (size_t)grow * K + q * 8, asz);
            cp16(stb + OFF_AL + dsw, Al + (size_t)grow * K + q * 8, asz);
            cp16(stb + OFF_BH + dsw, Bh + (size_t)r * K + q * 8);
            cp16(stb + OFF_BL + dsw, Bl + (size_t)r * K + q * 8);
        }
        asm volatile("cp.async.commit_group;" ::: "memory");
    };

    float acc[2][4][4];
    #pragma unroll
    for (int mt = 0; mt < 2; mt++)
        #pragma unroll
        for (int nt = 0; nt < 4; nt++)
            #pragma unroll
            for (int i = 0; i < 4; i++) acc[mt][nt][i] = 0.0f;

    // ldmatrix lane addressing
    const int laneA_r = lane & 15;                     // row within m16
    const int laneA_c = (lane >> 4) << 4;              // k8 select (bytes)
    // paired B x4: lanes 0-7 -> (nt0,k0), 8-15 -> (nt0,k8), 16-23 -> (nt1,k0), 24-31 -> (nt1,k8)
    const int laneB_r = (lane & 7) + (((lane >> 4) & 1) << 3);  // row within 16-row pair
    const int laneB_c = ((lane >> 3) & 1) << 4;

    // prologue: fill pipeline
    issue_chunk(0, 0);
    if (nchunks > 1) issue_chunk(1, 1);

    int stage = 0;
    for (int c = 0; c < nchunks; ++c) {
        if (c + 1 < nchunks)
            asm volatile("cp.async.wait_group 1;" ::: "memory");
        else
            asm volatile("cp.async.wait_group 0;" ::: "memory");
        __syncthreads();
        if (c + 2 < nchunks) {
            int s2 = stage + 2; if (s2 >= NSTAGE) s2 -= NSTAGE;
            issue_chunk(c + 2, s2);
        }

        const uint32_t stb = sbase + (uint32_t)(stage * STAGE);
        #pragma unroll
        for (int ks = 0; ks < 4; ks++) {
            const int ca = ks * 32;   // byte offset of k16 sub-tile within row

            uint32_t ah[2][4], al[2][4], bh[2][4], bl[2][4];
            #pragma unroll
            for (int mt = 0; mt < 2; mt++) {
                const int r = warp_m * 32 + mt * 16 + laneA_r;
                const uint32_t cc = (uint32_t)(ca + laneA_c) ^ (uint32_t)((r & 7) << 4);
                ldsm_x4(ah[mt], stb + OFF_AH + r * 128 + cc);
            }
            #pragma unroll
            for (int np = 0; np < 2; np++) {          // two n8 tiles per x4
                const int r = warp_n * 32 + np * 16 + laneB_r;
                const uint32_t cc = (uint32_t)(ca + laneB_c) ^ (uint32_t)((r & 7) << 4);
                ldsm_x4(bh[np], stb + OFF_BH + r * 128 + cc);
            }
            #pragma unroll
            for (int np = 0; np < 2; np++) {
                const int r = warp_n * 32 + np * 16 + laneB_r;
                const uint32_t cc = (uint32_t)(ca + laneB_c) ^ (uint32_t)((r & 7) << 4);
                ldsm_x4(bl[np], stb + OFF_BL + r * 128 + cc);
            }
            #pragma unroll
            for (int mt = 0; mt < 2; mt++) {
                const int r = warp_m * 32 + mt * 16 + laneA_r;
                const uint32_t cc = (uint32_t)(ca + laneA_c) ^ (uint32_t)((r & 7) << 4);
                ldsm_x4(al[mt], stb + OFF_AL + r * 128 + cc);
            }

            #pragma unroll
            for (int mt = 0; mt < 2; mt++)
                #pragma unroll
                for (int nt = 0; nt < 4; nt++)
                    mma16816(acc[mt][nt], ah[mt], &bh[nt >> 1][(nt & 1) * 2]);
            #pragma unroll
            for (int mt = 0; mt < 2; mt++)
                #pragma unroll
                for (int nt = 0; nt < 4; nt++)
                    mma16816(acc[mt][nt], ah[mt], &bl[nt >> 1][(nt & 1) * 2]);
            #pragma unroll
            for (int mt = 0; mt < 2; mt++)
                #pragma unroll
                for (int nt = 0; nt < 4; nt++)
                    mma16816(acc[mt][nt], al[mt], &bh[nt >> 1][(nt & 1) * 2]);
        }
        stage = (stage + 1 == NSTAGE) ? 0 : stage + 1;
    }

    // ---- epilogue: direct coalesced stores ----
    const int rbase = row0 + warp_m * 32 + (lane >> 2);
    const int cbase = col0 + warp_n * 32 + 2 * (lane & 3);
    #pragma unroll
    for (int mt = 0; mt < 2; mt++) {
        #pragma unroll
        for (int nt = 0; nt < 4; nt++) {
            const int r = rbase + mt * 16;
            const int cc = cbase + nt * 8;
            *reinterpret_cast<float2*>(&C[(size_t)r * N + cc]) =
                make_float2(acc[mt][nt][0], acc[mt][nt][1]);
            *reinterpret_cast<float2*>(&C[(size_t)(r + 8) * N + cc]) =
                make_float2(acc[mt][nt][2], acc[mt][nt][3]);
        }
    }
}

// ============================ launch ============================

extern "C" void kernel_launch(void* const* d_in, const int* in_sizes, int n_in,
                              void* d_out, int out_size) {
    const float* a   = (const float*)d_in[0];
    const float* b   = (const float*)d_in[1];
    const int*   gls = (const int*)d_in[2];
    float*       out = (float*)d_out;

    a_split<<<(M_TOTAL * K / 4) / 256, 256>>>(a);
    {
        dim3 grid(N / 32, K / 32, G);
        dim3 block(32, 8);
        b_transpose_split<<<grid, block>>>(b);
    }
    {
        cudaFuncSetAttribute(grouped_gemm_mma_kernel,
                             cudaFuncAttributeMaxDynamicSharedMemorySize, SMEM_BYTES);
        dim3 grid(N / BN, M_TOTAL / BM);   // (4, 128)
        grouped_gemm_mma_kernel<<<grid, NTHREADS, SMEM_BYTES>>>(gls, out);
    }
}

// round 10
// speedup vs baseline: 1.5113x; 1.5113x over previous
#include <cuda_runtime.h>
#include <cuda_fp16.h>
#include <cstdint>

static constexpr int M_TOTAL = 16384;
static constexpr int K = 512;
static constexpr int N = 512;
static constexpr int G = 8;

#define BM 128
#define BN 128
#define KC 64               // K chunk: 64 fp16 = 128 bytes/row (SW128 atom)
#define NTHREADS 256

// ---- pre-split scratch ----
__device__ __half g_Ah[(size_t)M_TOTAL * K];          // A hi (fp16)
__device__ __half g_Bh[(size_t)G * N * K];            // B^T hi (fp16), [g][n][k]
__device__ __half g_Bl[(size_t)G * N * K];            // B^T lo (fp16)

// ============================ helpers ============================

__device__ __forceinline__ uint32_t smem_u32(const void* p) {
    uint32_t a;
    asm("{ .reg .u64 t; cvta.to.shared.u64 t, %1; cvt.u32.u64 %0, t; }"
        : "=r"(a) : "l"(p));
    return a;
}

__device__ __forceinline__ void ldsm_x4(uint32_t* r, uint32_t addr) {
    asm volatile("ldmatrix.sync.aligned.m8n8.x4.shared.b16 {%0,%1,%2,%3}, [%4];"
                 : "=r"(r[0]), "=r"(r[1]), "=r"(r[2]), "=r"(r[3]) : "r"(addr));
}

__device__ __forceinline__ void mma16816(float* d, const uint32_t* a, const uint32_t* b) {
    asm volatile(
        "mma.sync.aligned.m16n8k16.row.col.f32.f16.f16.f32 "
        "{%0,%1,%2,%3}, {%4,%5,%6,%7}, {%8,%9}, {%0,%1,%2,%3};"
        : "+f"(d[0]), "+f"(d[1]), "+f"(d[2]), "+f"(d[3])
        : "r"(a[0]), "r"(a[1]), "r"(a[2]), "r"(a[3]), "r"(b[0]), "r"(b[1]));
}

__device__ __forceinline__ uint32_t swz128(uint32_t b) {
    return b ^ ((b >> 3) & 0x70);
}

__device__ __forceinline__ void cp16(uint32_t smem_dst, const void* gsrc, uint32_t srcbytes) {
    asm volatile("cp.async.cg.shared.global [%0], [%1], 16, %2;"
                 :: "r"(smem_dst), "l"(gsrc), "r"(srcbytes) : "memory");
}
__device__ __forceinline__ void cp16(uint32_t smem_dst, const void* gsrc) {
    asm volatile("cp.async.cg.shared.global [%0], [%1], 16;"
                 :: "r"(smem_dst), "l"(gsrc) : "memory");
}

// ============================ kernel 1a: A fp16-hi ============================

__global__ __launch_bounds__(256)
void a_split(const float* __restrict__ A) {
    const size_t idx = (size_t)blockIdx.x * 256 + threadIdx.x;   // float4 index
    const float4 v = reinterpret_cast<const float4*>(A)[idx];
    __half hx = __float2half_rn(v.x);
    __half hy = __float2half_rn(v.y);
    __half hz = __float2half_rn(v.z);
    __half hw = __float2half_rn(v.w);
    uint32_t h01, h23;
    asm("mov.b32 %0, {%1, %2};" : "=r"(h01) : "h"(__half_raw(hx).x), "h"(__half_raw(hy).x));
    asm("mov.b32 %0, {%1, %2};" : "=r"(h23) : "h"(__half_raw(hz).x), "h"(__half_raw(hw).x));
    reinterpret_cast<uint2*>(g_Ah)[idx] = make_uint2(h01, h23);
}

// ============================ kernel 1b: B transpose + fp16 hi/lo split ============================

__global__ __launch_bounds__(256)
void b_transpose_split(const float* __restrict__ B) {
    __shared__ float t[32][33];
    const int g  = blockIdx.z;
    const int k0 = blockIdx.y * 32;
    const int n0 = blockIdx.x * 32;
    const int x = threadIdx.x;
    const int y = threadIdx.y;
    const float* Bg = B + (size_t)g * K * N;
    #pragma unroll
    for (int i = 0; i < 4; i++)
        t[y + 8 * i][x] = Bg[(size_t)(k0 + y + 8 * i) * N + n0 + x];
    __syncthreads();
    #pragma unroll
    for (int i = 0; i < 4; i++) {
        const int n = n0 + y + 8 * i;
        const int k = k0 + x;
        float v = t[x][y + 8 * i];
        __half hi = __float2half_rn(v);
        __half lo = __float2half_rn(v - __half2float(hi));
        const size_t o = ((size_t)g * N + n) * K + k;
        g_Bh[o] = hi;
        g_Bl[o] = lo;
    }
}

// ============================ kernel 2: 2-stage pipelined grouped GEMM (fp16 x2) ============================

static constexpr int OFF_A  = 0;
static constexpr int OFF_BH = 16384;
static constexpr int OFF_BL = 2 * 16384;
static constexpr int STAGE  = 3 * 16384;          // 48 KB per stage
static constexpr int SMEM_BYTES = 1024 /*align slack*/ + 2 * STAGE;   // 97 KB

__global__ __launch_bounds__(NTHREADS, 2)
void grouped_gemm_mma_kernel(const int* __restrict__ glist,
                             float*     __restrict__ C) {
    extern __shared__ char dynsmem[];
    const uint32_t raw   = smem_u32(dynsmem);
    const uint32_t sbase = (raw + 1023u) & ~1023u;

    const int tid  = threadIdx.x;
    const int wid  = tid >> 5;
    const int lane = tid & 31;
    const int warp_m = wid >> 1;            // 0..3 -> 32-row slab
    const int warp_n = wid & 1;             // 0..1 -> 64-col slab
    const int row0 = blockIdx.y * BM;
    const int col0 = blockIdx.x * BN;

    int gl[G];
    #pragma unroll
    for (int g = 0; g < G; g++) gl[g] = glist[g];
    auto gid_of = [&](int row) {
        int g = 0;
        #pragma unroll
        for (int i = 0; i < G; i++) if (row >= gl[i]) g = i + 1;
        return g;
    };
    const int g0 = gid_of(row0);
    const int g1 = gid_of(row0 + BM - 1);
    const int nchunks = (g1 - g0 + 1) * (K / KC);

    auto issue_chunk = [&](int c, int s) {
        const int g  = g0 + (c >> 3);             // K/KC == 8
        const int kt = (c & 7) * KC;
        const int glo = (g == 0) ? 0 : gl[g - 1];
        const int ghi = gl[g];
        const __half* __restrict__ Ah = g_Ah + kt;
        const __half* __restrict__ Bh = g_Bh + ((size_t)g * N + col0) * K + kt;
        const __half* __restrict__ Bl = g_Bl + ((size_t)g * N + col0) * K + kt;
        const uint32_t stb = sbase + (uint32_t)(s * STAGE);
        #pragma unroll
        for (int i = 0; i < 4; i++) {
            const int idx = tid + i * NTHREADS;   // 0..1023
            const int r = idx >> 3;               // row 0..127
            const int q = idx & 7;                // 16B chunk 0..7
            const uint32_t dsw = swz128((uint32_t)(r * 128 + q * 16));
            const int grow = row0 + r;
            const uint32_t asz = (grow >= glo && grow < ghi) ? 16u : 0u;
            cp16(stb + OFF_A  + dsw, Ah + (size_t)grow * K + q * 8, asz);
            cp16(stb + OFF_BH + dsw, Bh + (size_t)r * K + q * 8);
            cp16(stb + OFF_BL + dsw, Bl + (size_t)r * K + q * 8);
        }
        asm volatile("cp.async.commit_group;" ::: "memory");
    };

    float acc[2][8][4];
    #pragma unroll
    for (int mt = 0; mt < 2; mt++)
        #pragma unroll
        for (int nt = 0; nt < 8; nt++)
            #pragma unroll
            for (int i = 0; i < 4; i++) acc[mt][nt][i] = 0.0f;

    // ldmatrix lane addressing
    const int laneA_r = lane & 15;
    const int laneA_c = (lane >> 4) << 4;
    // paired B x4: covers two n8 tiles (16 rows) per instruction
    const int laneB_r = (lane & 7) + (((lane >> 4) & 1) << 3);
    const int laneB_c = ((lane >> 3) & 1) << 4;

    issue_chunk(0, 0);

    int stage = 0;
    for (int c = 0; c < nchunks; ++c) {
        asm volatile("cp.async.wait_group 0;" ::: "memory");
        __syncthreads();
        if (c + 1 < nchunks) issue_chunk(c + 1, stage ^ 1);

        const uint32_t stb = sbase + (uint32_t)(stage * STAGE);
        #pragma unroll
        for (int ks = 0; ks < 4; ks++) {
            const int ca = ks * 32;   // byte offset of k16 sub-tile within row

            uint32_t ah[2][4], bh[4][4], bl[4][4];
            #pragma unroll
            for (int mt = 0; mt < 2; mt++) {
                const int r = warp_m * 32 + mt * 16 + laneA_r;
                const uint32_t cc = (uint32_t)(ca + laneA_c) ^ (uint32_t)((r & 7) << 4);
                ldsm_x4(ah[mt], stb + OFF_A + r * 128 + cc);
            }
            #pragma unroll
            for (int np = 0; np < 4; np++) {
                const int r = warp_n * 64 + np * 16 + laneB_r;
                const uint32_t cc = (uint32_t)(ca + laneB_c) ^ (uint32_t)((r & 7) << 4);
                ldsm_x4(bh[np], stb + OFF_BH + r * 128 + cc);
            }
            #pragma unroll
            for (int np = 0; np < 4; np++) {
                const int r = warp_n * 64 + np * 16 + laneB_r;
                const uint32_t cc = (uint32_t)(ca + laneB_c) ^ (uint32_t)((r & 7) << 4);
                ldsm_x4(bl[np], stb + OFF_BL + r * 128 + cc);
            }

            #pragma unroll
            for (int mt = 0; mt < 2; mt++)
                #pragma unroll
                for (int nt = 0; nt < 8; nt++)
                    mma16816(acc[mt][nt], ah[mt], &bh[nt >> 1][(nt & 1) * 2]);
            #pragma unroll
            for (int mt = 0; mt < 2; mt++)
                #pragma unroll
                for (int nt = 0; nt < 8; nt++)
                    mma16816(acc[mt][nt], ah[mt], &bl[nt >> 1][(nt & 1) * 2]);
        }
        stage ^= 1;
    }

    // ---- epilogue: direct coalesced stores ----
    const int rbase = row0 + warp_m * 32 + (lane >> 2);
    const int cbase = col0 + warp_n * 64 + 2 * (lane & 3);
    #pragma unroll
    for (int mt = 0; mt < 2; mt++) {
        #pragma unroll
        for (int nt = 0; nt < 8; nt++) {
            const int r = rbase + mt * 16;
            const int cc = cbase + nt * 8;
            *reinterpret_cast<float2*>(&C[(size_t)r * N + cc]) =
                make_float2(acc[mt][nt][0], acc[mt][nt][1]);
            *reinterpret_cast<float2*>(&C[(size_t)(r + 8) * N + cc]) =
                make_float2(acc[mt][nt][2], acc[mt][nt][3]);
        }
    }
}

// ============================ launch ============================

extern "C" void kernel_launch(void* const* d_in, const int* in_sizes, int n_in,
                              void* d_out, int out_size) {
    const float* a   = (const float*)d_in[0];
    const float* b   = (const float*)d_in[1];
    const int*   gls = (const int*)d_in[2];
    float*       out = (float*)d_out;

    a_split<<<(M_TOTAL * K / 4) / 256, 256>>>(a);
    {
        dim3 grid(N / 32, K / 32, G);
        dim3 block(32, 8);
        b_transpose_split<<<grid, block>>>(b);
    }
    {
        cudaFuncSetAttribute(grouped_gemm_mma_kernel,
                             cudaFuncAttributeMaxDynamicSharedMemorySize, SMEM_BYTES);
        dim3 grid(N / BN, M_TOTAL / BM);   // (4, 128)
        grouped_gemm_mma_kernel<<<grid, NTHREADS, SMEM_BYTES>>>(gls, out);
    }
}

// round 13
// speedup vs baseline: 1.5486x; 1.0247x over previous
#include <cuda_runtime.h>
#include <cuda_fp16.h>
#include <cstdint>

static constexpr int M_TOTAL = 16384;
static constexpr int K = 512;
static constexpr int N = 512;
static constexpr int G = 8;

#define BM 128
#define BN 128
#define KC 64               // K chunk: 64 fp16 = 128 bytes/row (SW128 atom)
#define NTHREADS 256

// ---- pre-split scratch ----
__device__ __half g_Ah[(size_t)M_TOTAL * K];          // A hi (fp16)
__device__ __half g_Bh[(size_t)G * N * K];            // B^T hi (fp16), [g][n][k]
__device__ __half g_Bl[(size_t)G * N * K];            // B^T lo (fp16)

// ============================ helpers ============================

__device__ __forceinline__ uint32_t smem_u32(const void* p) {
    uint32_t a;
    asm("{ .reg .u64 t; cvta.to.shared.u64 t, %1; cvt.u32.u64 %0, t; }"
        : "=r"(a) : "l"(p));
    return a;
}

__device__ __forceinline__ void ldsm_x4(uint32_t* r, uint32_t addr) {
    asm volatile("ldmatrix.sync.aligned.m8n8.x4.shared.b16 {%0,%1,%2,%3}, [%4];"
                 : "=r"(r[0]), "=r"(r[1]), "=r"(r[2]), "=r"(r[3]) : "r"(addr));
}

__device__ __forceinline__ void mma16816(float* d, const uint32_t* a, const uint32_t* b) {
    asm volatile(
        "mma.sync.aligned.m16n8k16.row.col.f32.f16.f16.f32 "
        "{%0,%1,%2,%3}, {%4,%5,%6,%7}, {%8,%9}, {%0,%1,%2,%3};"
        : "+f"(d[0]), "+f"(d[1]), "+f"(d[2]), "+f"(d[3])
        : "r"(a[0]), "r"(a[1]), "r"(a[2]), "r"(a[3]), "r"(b[0]), "r"(b[1]));
}

__device__ __forceinline__ uint32_t swz128(uint32_t b) {
    return b ^ ((b >> 3) & 0x70);
}

__device__ __forceinline__ void cp16(uint32_t smem_dst, const void* gsrc, uint32_t srcbytes) {
    asm volatile("cp.async.cg.shared.global [%0], [%1], 16, %2;"
                 :: "r"(smem_dst), "l"(gsrc), "r"(srcbytes) : "memory");
}
__device__ __forceinline__ void cp16(uint32_t smem_dst, const void* gsrc) {
    asm volatile("cp.async.cg.shared.global [%0], [%1], 16;"
                 :: "r"(smem_dst), "l"(gsrc) : "memory");
}

// ============================ kernel 1a: A fp16-hi (MLP=4) ============================

__global__ __launch_bounds__(256)
void a_split(const float* __restrict__ A) {
    const size_t base = (size_t)blockIdx.x * 1024 + threadIdx.x;   // float4 index
    float4 v[4];
    #pragma unroll
    for (int i = 0; i < 4; i++)
        v[i] = reinterpret_cast<const float4*>(A)[base + i * 256];
    #pragma unroll
    for (int i = 0; i < 4; i++) {
        __half hx = __float2half_rn(v[i].x);
        __half hy = __float2half_rn(v[i].y);
        __half hz = __float2half_rn(v[i].z);
        __half hw = __float2half_rn(v[i].w);
        uint32_t h01, h23;
        asm("mov.b32 %0, {%1, %2};" : "=r"(h01) : "h"(__half_raw(hx).x), "h"(__half_raw(hy).x));
        asm("mov.b32 %0, {%1, %2};" : "=r"(h23) : "h"(__half_raw(hz).x), "h"(__half_raw(hw).x));
        reinterpret_cast<uint2*>(g_Ah)[base + i * 256] = make_uint2(h01, h23);
    }
}

// ============================ kernel 1b: B transpose + fp16 hi/lo split ============================

__global__ __launch_bounds__(256)
void b_transpose_split(const float* __restrict__ B) {
    __shared__ float t[32][33];
    const int g  = blockIdx.z;
    const int k0 = blockIdx.y * 32;
    const int n0 = blockIdx.x * 32;
    const int x = threadIdx.x;
    const int y = threadIdx.y;
    const float* Bg = B + (size_t)g * K * N;
    #pragma unroll
    for (int i = 0; i < 4; i++)
        t[y + 8 * i][x] = Bg[(size_t)(k0 + y + 8 * i) * N + n0 + x];
    __syncthreads();
    #pragma unroll
    for (int i = 0; i < 4; i++) {
        const int n = n0 + y + 8 * i;
        const int k = k0 + x;
        float v = t[x][y + 8 * i];
        __half hi = __float2half_rn(v);
        __half lo = __float2half_rn(v - __half2float(hi));
        const size_t o = ((size_t)g * N + n) * K + k;
        g_Bh[o] = hi;
        g_Bl[o] = lo;
    }
}

// ============================ kernel 2: 2-stage pipelined grouped GEMM (fp16 x2) ============================

static constexpr int OFF_A  = 0;
static constexpr int OFF_BH = 16384;
static constexpr int OFF_BL = 2 * 16384;
static constexpr int STAGE  = 3 * 16384;          // 48 KB per stage
static constexpr int SMEM_BYTES = 1024 /*align slack*/ + 2 * STAGE;   // 97 KB

__global__ __launch_bounds__(NTHREADS, 2)
void grouped_gemm_mma_kernel(const int* __restrict__ glist,
                             float*     __restrict__ C) {
    extern __shared__ char dynsmem[];
    const uint32_t raw   = smem_u32(dynsmem);
    const uint32_t sbase = (raw + 1023u) & ~1023u;

    const int tid  = threadIdx.x;
    const int wid  = tid >> 5;
    const int lane = tid & 31;
    const int warp_m = wid & 1;             // 0..1 -> 64-row slab
    const int warp_n = wid >> 1;            // 0..3 -> 32-col slab
    const int row0 = blockIdx.y * BM;
    const int col0 = blockIdx.x * BN;

    int gl[G];
    #pragma unroll
    for (int g = 0; g < G; g++) gl[g] = glist[g];
    auto gid_of = [&](int row) {
        int g = 0;
        #pragma unroll
        for (int i = 0; i < G; i++) if (row >= gl[i]) g = i + 1;
        return g;
    };
    const int g0 = gid_of(row0);
    const int g1 = gid_of(row0 + BM - 1);
    const int nchunks = (g1 - g0 + 1) * (K / KC);

    auto issue_chunk = [&](int c, int s) {
        const int g  = g0 + (c >> 3);             // K/KC == 8
        const int kt = (c & 7) * KC;
        const int glo = (g == 0) ? 0 : gl[g - 1];
        const int ghi = gl[g];
        const __half* __restrict__ Ah = g_Ah + kt;
        const __half* __restrict__ Bh = g_Bh + ((size_t)g * N + col0) * K + kt;
        const __half* __restrict__ Bl = g_Bl + ((size_t)g * N + col0) * K + kt;
        const uint32_t stb = sbase + (uint32_t)(s * STAGE);
        #pragma unroll
        for (int i = 0; i < 4; i++) {
            const int idx = tid + i * NTHREADS;   // 0..1023
            const int r = idx >> 3;               // row 0..127
            const int q = idx & 7;                // 16B chunk 0..7
            const uint32_t dsw = swz128((uint32_t)(r * 128 + q * 16));
            const int grow = row0 + r;
            const uint32_t asz = (grow >= glo && grow < ghi) ? 16u : 0u;
            cp16(stb + OFF_A  + dsw, Ah + (size_t)grow * K + q * 8, asz);
            cp16(stb + OFF_BH + dsw, Bh + (size_t)r * K + q * 8);
            cp16(stb + OFF_BL + dsw, Bl + (size_t)r * K + q * 8);
        }
        asm volatile("cp.async.commit_group;" ::: "memory");
    };

    float acc[4][4][4];
    #pragma unroll
    for (int mt = 0; mt < 4; mt++)
        #pragma unroll
        for (int nt = 0; nt < 4; nt++)
            #pragma unroll
            for (int i = 0; i < 4; i++) acc[mt][nt][i] = 0.0f;

    // ldmatrix lane addressing
    const int laneA_r = lane & 15;
    const int laneA_c = (lane >> 4) << 4;
    // paired B x4: covers two n8 tiles (16 rows) per instruction
    const int laneB_r = (lane & 7) + (((lane >> 4) & 1) << 3);
    const int laneB_c = ((lane >> 3) & 1) << 4;

    issue_chunk(0, 0);

    int stage = 0;
    for (int c = 0; c < nchunks; ++c) {
        asm volatile("cp.async.wait_group 0;" ::: "memory");
        __syncthreads();
        if (c + 1 < nchunks) issue_chunk(c + 1, stage ^ 1);

        const uint32_t stb = sbase + (uint32_t)(stage * STAGE);
        #pragma unroll
        for (int ks = 0; ks < 4; ks++) {
            const int ca = ks * 32;   // byte offset of k16 sub-tile within row

            uint32_t ah[4][4];
            #pragma unroll
            for (int mt = 0; mt < 4; mt++) {
                const int r = warp_m * 64 + mt * 16 + laneA_r;
                const uint32_t cc = (uint32_t)(ca + laneA_c) ^ (uint32_t)((r & 7) << 4);
                ldsm_x4(ah[mt], stb + OFF_A + r * 128 + cc);
            }
            // --- hi product: load bh, consume immediately (short liveness) ---
            {
                uint32_t b[2][4];
                #pragma unroll
                for (int np = 0; np < 2; np++) {
                    const int r = warp_n * 32 + np * 16 + laneB_r;
                    const uint32_t cc = (uint32_t)(ca + laneB_c) ^ (uint32_t)((r & 7) << 4);
                    ldsm_x4(b[np], stb + OFF_BH + r * 128 + cc);
                }
                #pragma unroll
                for (int mt = 0; mt < 4; mt++)
                    #pragma unroll
                    for (int nt = 0; nt < 4; nt++)
                        mma16816(acc[mt][nt], ah[mt], &b[nt >> 1][(nt & 1) * 2]);
            }
            // --- lo product: reuse register space for bl ---
            {
                uint32_t b[2][4];
                #pragma unroll
                for (int np = 0; np < 2; np++) {
                    const int r = warp_n * 32 + np * 16 + laneB_r;
                    const uint32_t cc = (uint32_t)(ca + laneB_c) ^ (uint32_t)((r & 7) << 4);
                    ldsm_x4(b[np], stb + OFF_BL + r * 128 + cc);
                }
                #pragma unroll
                for (int mt = 0; mt < 4; mt++)
                    #pragma unroll
                    for (int nt = 0; nt < 4; nt++)
                        mma16816(acc[mt][nt], ah[mt], &b[nt >> 1][(nt & 1) * 2]);
            }
        }
        stage ^= 1;
    }

    // ---- epilogue: direct coalesced stores ----
    const int rbase = row0 + warp_m * 64 + (lane >> 2);
    const int cbase = col0 + warp_n * 32 + 2 * (lane & 3);
    #pragma unroll
    for (int mt = 0; mt < 4; mt++) {
        #pragma unroll
        for (int nt = 0; nt < 4; nt++) {
            const int r = rbase + mt * 16;
            const int cc = cbase + nt * 8;
            *reinterpret_cast<float2*>(&C[(size_t)r * N + cc]) =
                make_float2(acc[mt][nt][0], acc[mt][nt][1]);
            *reinterpret_cast<float2*>(&C[(size_t)(r + 8) * N + cc]) =
                make_float2(acc[mt][nt][2], acc[mt][nt][3]);
        }
    }
}

// ============================ launch ============================

extern "C" void kernel_launch(void* const* d_in, const int* in_sizes, int n_in,
                              void* d_out, int out_size) {
    const float* a   = (const float*)d_in[0];
    const float* b   = (const float*)d_in[1];
    const int*   gls = (const int*)d_in[2];
    float*       out = (float*)d_out;

    a_split<<<(M_TOTAL * K / 4) / 1024, 256>>>(a);
    {
        dim3 grid(N / 32, K / 32, G);
        dim3 block(32, 8);
        b_transpose_split<<<grid, block>>>(b);
    }
    {
        cudaFuncSetAttribute(grouped_gemm_mma_kernel,
                             cudaFuncAttributeMaxDynamicSharedMemorySize, SMEM_BYTES);
        dim3 grid(N / BN, M_TOTAL / BM);   // (4, 128)
        grouped_gemm_mma_kernel<<<grid, NTHREADS, SMEM_BYTES>>>(gls, out);
    }
}